// round 12
// baseline (speedup 1.0000x reference)
#include <cuda_runtime.h>
#include <cuda_bf16.h>
#include <cstdint>

// =====================================================================
// GraphConv on GB300 — family-generic PTX (no tcgen05 on compute_103).
// mma.sync m16n8k16 bf16 + ldmatrix + swizzled smem.
//   out = relu(F@W1 + A@(F@W2) + bias)
// P1: weight prep; P2: Gt = W2^T@F^T; P3: fused K=2816 GEMM.
// P3: M128 x N128, 256 thr, 2 CTA/SM, KC=32, depth-3 cp.async B ring,
//     A LDG-prefetched 2 chunks ahead. One bar/chunk.
// =====================================================================

#define BATCH 16
#define NTOK  2048
#define DDIM  256
#define FDIM  256
#define KAUG  768
#define KC2   32
#define NCH   88    // 2816/32

__device__ __nv_bfloat16 g_Gt[(size_t)BATCH * FDIM * NTOK];  // [b][f][tok]
__device__ __nv_bfloat16 g_W2t[FDIM * DDIM];                 // [f][d]
__device__ __nv_bfloat16 g_Bw[FDIM * KAUG];                  // [f][Wh|Wl|Wh]

#define SW128(o) ((o) ^ (((o) >> 3) & 0x70))
#define SW64(o)  ((o) ^ (((o) >> 3) & 0x30))

// ---- P2 smem (256 thr, M128xN128, KC=64, 128B pitch): A0|A1|B0|B1 ----
#define TILE128 16384
#define SMEM_P2 (4 * TILE128)
// ---- P3 smem (KC=32, 64B pitch): A[2] 8KB | B[4] 8KB = 48KB ----
#define TILE64 8192
#define P3_A0  0
#define P3_B0  (2 * TILE64)
#define P3_SMEM (6 * TILE64)

__device__ __forceinline__ uint32_t smem_to_u32(const void* p) {
    uint32_t a;
    asm("{ .reg .u64 t; cvta.to.shared.u64 t, %1; cvt.u32.u64 %0, t; }"
        : "=r"(a) : "l"(p));
    return a;
}
__device__ __forceinline__ void ldsm_x4(uint32_t addr, uint32_t r[4]) {
    asm volatile("ldmatrix.sync.aligned.m8n8.x4.shared.b16 {%0,%1,%2,%3}, [%4];"
                 : "=r"(r[0]), "=r"(r[1]), "=r"(r[2]), "=r"(r[3]) : "r"(addr));
}
__device__ __forceinline__ void mma_16816(float c[4], const uint32_t a[4],
                                          uint32_t b0, uint32_t b1) {
    asm volatile(
        "mma.sync.aligned.m16n8k16.row.col.f32.bf16.bf16.f32 "
        "{%0,%1,%2,%3}, {%4,%5,%6,%7}, {%8,%9}, {%0,%1,%2,%3};"
        : "+f"(c[0]), "+f"(c[1]), "+f"(c[2]), "+f"(c[3])
        : "r"(a[0]), "r"(a[1]), "r"(a[2]), "r"(a[3]), "r"(b0), "r"(b1));
}
__device__ __forceinline__ void cp_async16(uint32_t saddr, const void* g) {
    asm volatile("cp.async.cg.shared.global [%0], [%1], 16;"
                 :: "r"(saddr), "l"(g));
}
#define CP_COMMIT() asm volatile("cp.async.commit_group;" ::: "memory")
#define CP_WAIT(n)  asm volatile("cp.async.wait_group %0;" :: "n"(n) : "memory")

__device__ __forceinline__ uint2 pack_bf4(float a, float b, float c, float d) {
    __nv_bfloat162 p0, p1;
    p0.x = __float2bfloat16(a); p0.y = __float2bfloat16(b);
    p1.x = __float2bfloat16(c); p1.y = __float2bfloat16(d);
    uint2 v;
    v.x = *reinterpret_cast<uint32_t*>(&p0);
    v.y = *reinterpret_cast<uint32_t*>(&p1);
    return v;
}
__device__ __forceinline__ float lo_part(float v) {
    return v - __bfloat162float(__float2bfloat16(v));
}

// =====================================================================
// P2 helpers (KC=64, 128B pitch) — unchanged from the 264.9us baseline
// =====================================================================
__device__ __forceinline__ void produce_f32_256(char* tile, const float* src,
                                                int stride_f, int tid) {
#pragma unroll
    for (int it = 0; it < 8; it++) {
        int lin = it * 256 + tid;
        int r = lin >> 4, c4 = lin & 15;
        float4 v = *reinterpret_cast<const float4*>(src + (size_t)r * stride_f + c4 * 4);
        uint2 w = pack_bf4(v.x, v.y, v.z, v.w);
        *reinterpret_cast<uint2*>(tile + SW128((uint32_t)(r * 128 + c4 * 8))) = w;
    }
}
__device__ __forceinline__ void produce_bf16_256(char* tile, const __nv_bfloat16* src,
                                                 int stride_e, int tid) {
#pragma unroll
    for (int it = 0; it < 4; it++) {
        int lin = it * 256 + tid;
        int r = lin >> 3, cv = lin & 7;
        uint4 v = *reinterpret_cast<const uint4*>(src + (size_t)r * stride_e + cv * 8);
        *reinterpret_cast<uint4*>(tile + SW128((uint32_t)(r * 128 + cv * 16))) = v;
    }
}
__device__ __forceinline__ void consume_chunk128(uint32_t aBase, uint32_t bBase,
                                                 int wm, int wn, int lane,
                                                 float acc[2][8][4]) {
    int arow = wm * 32 + (lane & 15);
    int akb  = ((lane >> 4) & 1) * 16;
    int bn   = (lane & 7) + ((lane >> 4) << 3);
    int bkb  = ((lane >> 3) & 1) * 16;
#pragma unroll
    for (int ks = 0; ks < 4; ks++) {
        uint32_t a[2][4];
#pragma unroll
        for (int mt = 0; mt < 2; mt++) {
            uint32_t off = (uint32_t)((arow + mt * 16) * 128 + ks * 32 + akb);
            ldsm_x4(aBase + SW128(off), a[mt]);
        }
#pragma unroll
        for (int ntp = 0; ntp < 4; ntp++) {
            uint32_t off = (uint32_t)((wn * 64 + ntp * 16 + bn) * 128 + ks * 32 + bkb);
            uint32_t bq[4];
            ldsm_x4(bBase + SW128(off), bq);
#pragma unroll
            for (int mt = 0; mt < 2; mt++) {
                mma_16816(acc[mt][2 * ntp],     a[mt], bq[0], bq[1]);
                mma_16816(acc[mt][2 * ntp + 1], a[mt], bq[2], bq[3]);
            }
        }
    }
}

// =====================================================================
// P3 helpers (KC=32, 64B pitch)
// =====================================================================
// A prefetch: 1024 float4 / 256 thr = 4/thread (16 regs)
__device__ __forceinline__ void p3_lda32(float4 v[4], const float* __restrict__ A,
                                         const float* __restrict__ F,
                                         int b, int mbase, int kbase, int tid)
{
    const float* src;
    int stride;
    if (kbase < 2048) {
        src = A + ((size_t)b * NTOK + mbase) * NTOK + kbase;
        stride = NTOK;
    } else {
        src = F + ((size_t)b * NTOK + mbase) * DDIM + ((kbase - 2048) & 255);
        stride = DDIM;
    }
#pragma unroll
    for (int i = 0; i < 4; i++) {
        int lin = i * 256 + tid;
        int r = lin >> 3, c4 = lin & 7;
        v[i] = *reinterpret_cast<const float4*>(src + (size_t)r * stride + c4 * 4);
    }
}
__device__ __forceinline__ void p3_sts_a32(char* tile, const float4 v[4],
                                           bool lo, int tid)
{
#pragma unroll
    for (int i = 0; i < 4; i++) {
        int lin = i * 256 + tid;
        int r = lin >> 3, c4 = lin & 7;
        float4 w = v[i];
        if (lo) {
            w.x = lo_part(w.x); w.y = lo_part(w.y);
            w.z = lo_part(w.z); w.w = lo_part(w.w);
        }
        uint2 pk = pack_bf4(w.x, w.y, w.z, w.w);
        *reinterpret_cast<uint2*>(tile + SW64((uint32_t)(r * 64 + c4 * 8))) = pk;
    }
}
// B cp.async: 512 uint4 / 256 thr = 2/thread
__device__ __forceinline__ void p3_cpa_b32(uint32_t bt, int b, int nbase,
                                           int kbase, int tid)
{
    const __nv_bfloat16* src;
    int stride;
    if (kbase < 2048) {
        src = g_Gt + ((size_t)b * FDIM + nbase) * NTOK + kbase;
        stride = NTOK;
    } else {
        src = g_Bw + (size_t)nbase * KAUG + (kbase - 2048);
        stride = KAUG;
    }
#pragma unroll
    for (int i = 0; i < 2; i++) {
        int lin = i * 256 + tid;
        int r = lin >> 2, cv = lin & 3;
        uint32_t d = bt + SW64((uint32_t)(r * 64 + cv * 16));
        cp_async16(d, src + (size_t)r * stride + cv * 8);
    }
}
__device__ __forceinline__ void consume_chunk32(uint32_t aBase, uint32_t bBase,
                                                int wm, int wn, int lane,
                                                float acc[2][8][4]) {
    int arow = wm * 32 + (lane & 15);
    int akb  = ((lane >> 4) & 1) * 16;
    int bn   = (lane & 7) + ((lane >> 4) << 3);
    int bkb  = ((lane >> 3) & 1) * 16;
#pragma unroll
    for (int ks = 0; ks < 2; ks++) {
        uint32_t a[2][4];
#pragma unroll
        for (int mt = 0; mt < 2; mt++) {
            uint32_t off = (uint32_t)((arow + mt * 16) * 64 + ks * 32 + akb);
            ldsm_x4(aBase + SW64(off), a[mt]);
        }
#pragma unroll
        for (int ntp = 0; ntp < 4; ntp++) {
            uint32_t off = (uint32_t)((wn * 64 + ntp * 16 + bn) * 64 + ks * 32 + bkb);
            uint32_t bq[4];
            ldsm_x4(bBase + SW64(off), bq);
#pragma unroll
            for (int mt = 0; mt < 2; mt++) {
                mma_16816(acc[mt][2 * ntp],     a[mt], bq[0], bq[1]);
                mma_16816(acc[mt][2 * ntp + 1], a[mt], bq[2], bq[3]);
            }
        }
    }
}

// =====================================================================
// P1: weight prep
// =====================================================================
__global__ void prep_weights_kernel(const float* __restrict__ w)
{
    int i = blockIdx.x * blockDim.x + threadIdx.x;
    if (i >= FDIM * DDIM) return;
    int n = i / DDIM, d = i % DDIM;
    float w1 = w[d * FDIM + n];
    float w2 = w[(DDIM + d) * FDIM + n];
    __nv_bfloat16 h = __float2bfloat16(w1);
    __nv_bfloat16 l = __float2bfloat16(w1 - __bfloat162float(h));
    g_Bw[n * KAUG + d]       = h;
    g_Bw[n * KAUG + 256 + d] = l;
    g_Bw[n * KAUG + 512 + d] = h;
    g_W2t[n * DDIM + d] = __float2bfloat16(w2);
}

// =====================================================================
// P2: Gt = W2^T @ F^T  (M=128 f, N=128 tok, K=256) — baseline version
// grid (16, 2, 16), block 256
// =====================================================================
__global__ void __launch_bounds__(256, 2)
gemm_gt_kernel(const float* __restrict__ F)
{
    extern __shared__ char smem[];
    uint32_t smem_u = smem_to_u32(smem);
    int tid = threadIdx.x;
    int wid = tid >> 5, lane = tid & 31;
    int wm = wid & 3, wn = wid >> 2;
    int ntile = blockIdx.x, mtile = blockIdx.y, b = blockIdx.z;
    int mbase = mtile * 128, nbase = ntile * 128;

    float acc[2][8][4];
#pragma unroll
    for (int i = 0; i < 2; i++)
#pragma unroll
        for (int j = 0; j < 8; j++)
#pragma unroll
            for (int q = 0; q < 4; q++) acc[i][j][q] = 0.f;

    for (int ch = 0; ch < 4; ch++) {
        int p = ch & 1;
        int kbase = ch * 64;
        char* at = smem + p * TILE128;
        char* bt = smem + (2 + p) * TILE128;
        produce_bf16_256(at, g_W2t + (size_t)mbase * DDIM + kbase, DDIM, tid);
        produce_f32_256(bt, F + ((size_t)b * NTOK + nbase) * DDIM + kbase, DDIM, tid);
        __syncthreads();
        consume_chunk128(smem_u + p * TILE128,
                         smem_u + (2 + p) * TILE128, wm, wn, lane, acc);
        __syncthreads();
    }

    int tg = lane >> 2, tc = (lane & 3) * 2;
#pragma unroll
    for (int mt = 0; mt < 2; mt++) {
        int f = mbase + wm * 32 + mt * 16 + tg;
        __nv_bfloat16* g0 = g_Gt + ((size_t)b * FDIM + f) * NTOK;
        __nv_bfloat16* g1 = g0 + (size_t)8 * NTOK;
#pragma unroll
        for (int nt = 0; nt < 8; nt++) {
            int col = nbase + wn * 64 + nt * 8 + tc;
            __nv_bfloat162 v0, v1;
            v0.x = __float2bfloat16(acc[mt][nt][0]);
            v0.y = __float2bfloat16(acc[mt][nt][1]);
            v1.x = __float2bfloat16(acc[mt][nt][2]);
            v1.y = __float2bfloat16(acc[mt][nt][3]);
            *reinterpret_cast<__nv_bfloat162*>(g0 + col) = v0;
            *reinterpret_cast<__nv_bfloat162*>(g1 + col) = v1;
        }
    }
}

// =====================================================================
// P3: out = relu([A|Fh|Fh|Fl] @ [Gt;Wh;Wl;Wh]^T + bias)
//   M=128 x N=128, KC=32, 88 chunks; depth-3 cp.async B; A prefetch.
// grid (2, 16, 16), block 256, 2 CTA/SM
// =====================================================================
__global__ void __launch_bounds__(256, 2)
gemm_big_kernel(const float* __restrict__ A, const float* __restrict__ F,
                const float* __restrict__ bias, float* __restrict__ out)
{
    extern __shared__ char smem[];
    uint32_t smem_u = smem_to_u32(smem);
    int tid = threadIdx.x;
    int wid = tid >> 5, lane = tid & 31;
    int wm = wid & 3, wn = wid >> 2;
    int ntile = blockIdx.x, mtile = blockIdx.y, b = blockIdx.z;
    int mbase = mtile * 128, nbase = ntile * 128;

    float acc[2][8][4];
#pragma unroll
    for (int i = 0; i < 2; i++)
#pragma unroll
        for (int j = 0; j < 8; j++)
#pragma unroll
            for (int q = 0; q < 4; q++) acc[i][j][q] = 0.f;

    float4 areg[2][4];

    // ---- prologue ----
    p3_lda32(areg[0], A, F, b, mbase, 0, tid);
    p3_cpa_b32(smem_u + P3_B0 + 0 * TILE64, b, nbase, 0 * KC2, tid); CP_COMMIT();
    p3_cpa_b32(smem_u + P3_B0 + 1 * TILE64, b, nbase, 1 * KC2, tid); CP_COMMIT();
    p3_cpa_b32(smem_u + P3_B0 + 2 * TILE64, b, nbase, 2 * KC2, tid); CP_COMMIT();
    p3_sts_a32(smem + P3_A0, areg[0], false, tid);
    p3_lda32(areg[1], A, F, b, mbase, 1 * KC2, tid);
    CP_WAIT(2);              // B0 complete
    __syncthreads();

    for (int ch = 0; ch < NCH; ch++) {
        if (ch + 2 < NCH)
            p3_lda32(areg[ch & 1], A, F, b, mbase, (ch + 2) * KC2, tid);
        if (ch + 3 < NCH) {
            p3_cpa_b32(smem_u + P3_B0 + ((ch + 3) & 3) * TILE64,
                       b, nbase, (ch + 3) * KC2, tid);
            CP_COMMIT();
        }
        consume_chunk32(smem_u + P3_A0 + (ch & 1) * TILE64,
                        smem_u + P3_B0 + (ch & 3) * TILE64, wm, wn, lane, acc);
        if (ch + 1 < NCH)
            p3_sts_a32(smem + P3_A0 + ((ch + 1) & 1) * TILE64,
                       areg[(ch + 1) & 1], (ch + 1) >= 80, tid);
        // ensure B(ch+1) complete before next iteration's consume
        if (ch <= NCH - 4)      CP_WAIT(2);
        else if (ch == NCH - 3) CP_WAIT(1);
        else if (ch == NCH - 2) CP_WAIT(0);
        __syncthreads();
    }

    // ---- epilogue: +bias, relu, fp32 stores ----
    int tg = lane >> 2, tc = (lane & 3) * 2;
#pragma unroll
    for (int mt = 0; mt < 2; mt++) {
        int r0 = mbase + wm * 32 + mt * 16 + tg;
        float* row0 = out + ((size_t)b * NTOK + r0) * FDIM;
        float* row1 = row0 + (size_t)8 * FDIM;
#pragma unroll
        for (int nt = 0; nt < 8; nt++) {
            int col = nbase + wn * 64 + nt * 8 + tc;
            float bb0 = __ldg(bias + col), bb1 = __ldg(bias + col + 1);
            float2 v0, v1;
            v0.x = fmaxf(acc[mt][nt][0] + bb0, 0.f);
            v0.y = fmaxf(acc[mt][nt][1] + bb1, 0.f);
            v1.x = fmaxf(acc[mt][nt][2] + bb0, 0.f);
            v1.y = fmaxf(acc[mt][nt][3] + bb1, 0.f);
            *reinterpret_cast<float2*>(row0 + col) = v0;
            *reinterpret_cast<float2*>(row1 + col) = v1;
        }
    }
}

// =====================================================================
// Launch
// =====================================================================
extern "C" void kernel_launch(void* const* d_in, const int* in_sizes, int n_in,
                              void* d_out, int out_size)
{
    const float* F    = (const float*)d_in[0];   // [16,2048,256]
    const float* A    = (const float*)d_in[1];   // [16,2048,2048]
    const float* W    = (const float*)d_in[2];   // [512,256]
    const float* bias = (const float*)d_in[3];   // [256]
    float* out = (float*)d_out;                  // [16,2048,256]

    cudaFuncSetAttribute(gemm_gt_kernel,
                         cudaFuncAttributeMaxDynamicSharedMemorySize, SMEM_P2);
    cudaFuncSetAttribute(gemm_big_kernel,
                         cudaFuncAttributeMaxDynamicSharedMemorySize, P3_SMEM);

    prep_weights_kernel<<<256, 256>>>(W);
    gemm_gt_kernel<<<dim3(16, 2, 16), 256, SMEM_P2>>>(F);
    gemm_big_kernel<<<dim3(2, 16, 16), 256, P3_SMEM>>>(A, F, bias, out);
}